// round 6
// baseline (speedup 1.0000x reference)
#include <cuda_runtime.h>

// x (B,N,1) f32, indices (2,NNZ) i32, values (NNZ,) f32, bias (M,1) f32
//   -> out (B,M,1) f32
#define NN   100000
#define MM   100000
#define NNZ  3200000
#define BB   32
// NN and MM are exact multiples of 32 (3125 tiles), NNZ is even.

// Scratch in batch-contiguous layout:
// xt[n*32 + b] = x[b*N + n];  yt[m*32 + b] accumulates, then transposed out.
__device__ float g_xt[(size_t)NN * BB];
__device__ float g_yt[(size_t)MM * BB];

// ---------------------------------------------------------------------------
// Kernel 1: transpose x (B,N) -> xt (N,B) and zero yt. Canonical tiled
// transpose: block (32,8), 4 rows per thread => MLP=4 before the barrier.
// ---------------------------------------------------------------------------
__global__ void k_transpose_in(const float* __restrict__ x) {
    __shared__ float tile[32][33];
    const int n0 = blockIdx.x * 32;
    const int tx = threadIdx.x;     // n_local on load, b on store
    const int ty = threadIdx.y;     // 0..7

    #pragma unroll
    for (int j = 0; j < 4; j++) {
        const int b = ty + 8 * j;
        tile[b][tx] = x[(size_t)b * NN + n0 + tx];      // coalesced over tx
    }
    __syncthreads();
    #pragma unroll
    for (int j = 0; j < 4; j++) {
        const int n = n0 + ty + 8 * j;
        g_xt[(size_t)n * BB + tx] = tile[tx][ty + 8 * j]; // coalesced over tx=b
        g_yt[(size_t)n * BB + tx] = 0.0f;                  // zero accumulator
    }
}

// ---------------------------------------------------------------------------
// Kernel 2: edge scatter. 8 threads per edge-pair-slot; each thread owns a
// float4 of the 32 batches for TWO edges (e and e+NNZ/2) => 2 independent
// 128B gathers in flight before the vector reductions.
// ---------------------------------------------------------------------------
__global__ void k_scatter(const int* __restrict__ indices,
                          const float* __restrict__ values) {
    const long long t  = (long long)blockIdx.x * blockDim.x + threadIdx.x;
    const long long e0 = t >> 3;
    const int       q  = (int)(t & 7);
    if (e0 >= (NNZ / 2)) return;
    const long long e1 = e0 + (NNZ / 2);

    const int   s0 = __ldg(indices + e0);
    const int   s1 = __ldg(indices + e1);
    const int   d0 = __ldg(indices + (long long)NNZ + e0);
    const int   d1 = __ldg(indices + (long long)NNZ + e1);
    const float v0 = __ldg(values + e0);
    const float v1 = __ldg(values + e1);

    // Issue both gathers before consuming either (MLP=2 x 128B).
    const float4 a = reinterpret_cast<const float4*>(g_xt)[(size_t)s0 * 8 + q];
    const float4 b = reinterpret_cast<const float4*>(g_xt)[(size_t)s1 * 8 + q];

    float4* p0 = reinterpret_cast<float4*>(g_yt) + (size_t)d0 * 8 + q;
    float4* p1 = reinterpret_cast<float4*>(g_yt) + (size_t)d1 * 8 + q;

    asm volatile("red.global.add.v4.f32 [%0], {%1, %2, %3, %4};"
                 :: "l"(p0), "f"(v0 * a.x), "f"(v0 * a.y),
                    "f"(v0 * a.z), "f"(v0 * a.w) : "memory");
    asm volatile("red.global.add.v4.f32 [%0], {%1, %2, %3, %4};"
                 :: "l"(p1), "f"(v1 * b.x), "f"(v1 * b.y),
                    "f"(v1 * b.z), "f"(v1 * b.w) : "memory");
}

// ---------------------------------------------------------------------------
// Kernel 3: transpose yt (M,B) -> out (B,M) + bias. Same canonical scheme.
// ---------------------------------------------------------------------------
__global__ void k_transpose_out(float* __restrict__ out,
                                const float* __restrict__ bias) {
    __shared__ float tile[32][33];
    const int m0 = blockIdx.x * 32;
    const int tx = threadIdx.x;
    const int ty = threadIdx.y;

    #pragma unroll
    for (int j = 0; j < 4; j++) {
        const int m = m0 + ty + 8 * j;
        tile[ty + 8 * j][tx] = g_yt[(size_t)m * BB + tx];  // coalesced, tx=b
    }
    __syncthreads();
    const float bv = bias[m0 + tx];
    #pragma unroll
    for (int j = 0; j < 4; j++) {
        const int b = ty + 8 * j;
        out[(size_t)b * MM + m0 + tx] = tile[tx][b] + bv;  // coalesced over tx=m
    }
}

extern "C" void kernel_launch(void* const* d_in, const int* in_sizes, int n_in,
                              void* d_out, int out_size) {
    const float* x       = (const float*)d_in[0];   // (B, N, 1)
    const int*   indices = (const int*)  d_in[1];   // (2, NNZ)
    const float* values  = (const float*)d_in[2];   // (NNZ,)
    const float* bias    = (const float*)d_in[3];   // (M, 1)
    float*       out     = (float*)d_out;           // (B, M, 1)

    (void)in_sizes; (void)n_in; (void)out_size;

    {   // 1) transpose x -> xt, zero yt   (NN/32 = 3125 tiles, exact)
        dim3 blk(32, 8);
        k_transpose_in<<<NN / 32, blk>>>(x);
    }
    {   // 2) edge scatter: (NNZ/2) * 8 threads, 2 edges per thread
        const long long total = (long long)(NNZ / 2) * 8;
        const int threads = 256;
        const int blocks = (int)((total + threads - 1) / threads);
        k_scatter<<<blocks, threads>>>(indices, values);
    }
    {   // 3) transpose yt -> out (+bias)
        dim3 blk(32, 8);
        k_transpose_out<<<MM / 32, blk>>>(out, bias);
    }
}

// round 7
// speedup vs baseline: 1.0172x; 1.0172x over previous
#include <cuda_runtime.h>

// x (B,N,1) f32, indices (2,NNZ) i32, values (NNZ,) f32, bias (M,1) f32
//   -> out (B,M,1) f32
#define NN    100000
#define MM    100000
#define NNZ   3200000
#define BB    32
#define CHUNK 512
#define NCHUNK ((MM + CHUNK - 1) / CHUNK)   // 196

// ---- device scratch (static, no allocs) -----------------------------------
__device__ float g_xt[(size_t)NN * BB];      // x transposed: (N, B)
__device__ float g_yt[(size_t)MM * BB];      // accumulator:  (M, B)
__device__ int   g_count[MM];                // per-dst degree
__device__ int   g_start[MM + 1];            // CSR row starts
__device__ int   g_cursor[MM];               // reorder write cursors
__device__ int   g_chunkoff[NCHUNK];         // scan chunk offsets
__device__ int   g_chunksum[NCHUNK];
__device__ int2  g_edge[NNZ];                // (src, val-as-int) sorted by dst

// ---------------------------------------------------------------------------
// 1) transpose x (B,N) -> xt (N,B); also zero g_count for this call.
//    Block (32,8), 4 rows/thread; NN % 32 == 0.
// ---------------------------------------------------------------------------
__global__ void k_transpose_in(const float* __restrict__ x) {
    __shared__ float tile[32][33];
    const int n0 = blockIdx.x * 32;
    const int tx = threadIdx.x, ty = threadIdx.y;

    #pragma unroll
    for (int j = 0; j < 4; j++) {
        const int b = ty + 8 * j;
        tile[b][tx] = x[(size_t)b * NN + n0 + tx];
    }
    // zero counts: 3125 blocks x 256 threads = 800k >= MM
    const int tid = blockIdx.x * 256 + ty * 32 + tx;
    if (tid < MM) g_count[tid] = 0;
    __syncthreads();
    #pragma unroll
    for (int j = 0; j < 4; j++) {
        const int n = n0 + ty + 8 * j;
        g_xt[(size_t)n * BB + tx] = tile[tx][ty + 8 * j];
    }
}

// ---------------------------------------------------------------------------
// 2) histogram of dst (4 edges/thread, int4 loads; NNZ % 4 == 0)
// ---------------------------------------------------------------------------
__global__ void k_hist(const int* __restrict__ indices) {
    const int t = blockIdx.x * blockDim.x + threadIdx.x;
    if (t >= NNZ / 4) return;
    const int4 d = reinterpret_cast<const int4*>(indices + NNZ)[t];
    atomicAdd(&g_count[d.x], 1);
    atomicAdd(&g_count[d.y], 1);
    atomicAdd(&g_count[d.z], 1);
    atomicAdd(&g_count[d.w], 1);
}

// ---------------------------------------------------------------------------
// 3a) per-chunk sums
// ---------------------------------------------------------------------------
__global__ void k_scan_a() {
    __shared__ int sm[CHUNK];
    const int t = threadIdx.x;
    const int idx = blockIdx.x * CHUNK + t;
    sm[t] = (idx < MM) ? g_count[idx] : 0;
    __syncthreads();
    for (int d = CHUNK / 2; d > 0; d >>= 1) {
        if (t < d) sm[t] += sm[t + d];
        __syncthreads();
    }
    if (t == 0) g_chunksum[blockIdx.x] = sm[0];
}

// 3b) scan the 196 chunk sums (one block)
__global__ void k_scan_b() {
    __shared__ int sm[256];
    const int t = threadIdx.x;
    int v = (t < NCHUNK) ? g_chunksum[t] : 0;
    sm[t] = v;
    __syncthreads();
    for (int d = 1; d < 256; d <<= 1) {
        int u = (t >= d) ? sm[t - d] : 0;
        __syncthreads();
        sm[t] += u;
        __syncthreads();
    }
    if (t < NCHUNK) g_chunkoff[t] = sm[t] - v;   // exclusive
}

// 3c) in-chunk exclusive scan + chunk offset -> g_start, g_cursor
__global__ void k_scan_c() {
    __shared__ int sm[CHUNK];
    const int t = threadIdx.x;
    const int idx = blockIdx.x * CHUNK + t;
    const int v = (idx < MM) ? g_count[idx] : 0;
    sm[t] = v;
    __syncthreads();
    for (int d = 1; d < CHUNK; d <<= 1) {
        int u = (t >= d) ? sm[t - d] : 0;
        __syncthreads();
        sm[t] += u;
        __syncthreads();
    }
    if (idx < MM) {
        const int s = g_chunkoff[blockIdx.x] + sm[t] - v;
        g_start[idx]  = s;
        g_cursor[idx] = s;
    }
    if (blockIdx.x == 0 && t == 0) g_start[MM] = NNZ;
}

// ---------------------------------------------------------------------------
// 4) reorder edges into dst-grouped order, payload packed as int2 (src, val)
// ---------------------------------------------------------------------------
__global__ void k_reorder(const int* __restrict__ indices,
                          const float* __restrict__ values) {
    const int e = blockIdx.x * blockDim.x + threadIdx.x;
    if (e >= NNZ) return;
    const int src = indices[e];
    const int dst = indices[NNZ + e];
    const int pos = atomicAdd(&g_cursor[dst], 1);
    g_edge[pos] = make_int2(src, __float_as_int(values[e]));
}

// ---------------------------------------------------------------------------
// 5) accumulate: one warp per dst; lane = batch. Cooperative 32-edge chunks,
//    shfl-broadcast src/val, 4-way unrolled gathers with 4 accumulators.
// ---------------------------------------------------------------------------
__global__ void k_accum() {
    const int m = blockIdx.x * (blockDim.x >> 5) + (threadIdx.x >> 5);
    const int lane = threadIdx.x & 31;
    if (m >= MM) return;

    const int s = g_start[m];
    const int e = g_start[m + 1];

    float a0 = 0.f, a1 = 0.f, a2 = 0.f, a3 = 0.f;

    for (int base = s; base < e; base += 32) {
        const int cnt = min(32, e - base);
        int2 ed = make_int2(0, 0);
        if (lane < cnt) ed = g_edge[base + lane];

        int j = 0;
        for (; j + 4 <= cnt; j += 4) {
            const int   s0 = __shfl_sync(0xffffffffu, ed.x, j + 0);
            const int   s1 = __shfl_sync(0xffffffffu, ed.x, j + 1);
            const int   s2 = __shfl_sync(0xffffffffu, ed.x, j + 2);
            const int   s3 = __shfl_sync(0xffffffffu, ed.x, j + 3);
            const float v0 = __int_as_float(__shfl_sync(0xffffffffu, ed.y, j + 0));
            const float v1 = __int_as_float(__shfl_sync(0xffffffffu, ed.y, j + 1));
            const float v2 = __int_as_float(__shfl_sync(0xffffffffu, ed.y, j + 2));
            const float v3 = __int_as_float(__shfl_sync(0xffffffffu, ed.y, j + 3));
            // 4 independent coalesced 128B gathers in flight
            const float x0 = g_xt[(size_t)s0 * BB + lane];
            const float x1 = g_xt[(size_t)s1 * BB + lane];
            const float x2 = g_xt[(size_t)s2 * BB + lane];
            const float x3 = g_xt[(size_t)s3 * BB + lane];
            a0 = fmaf(v0, x0, a0);
            a1 = fmaf(v1, x1, a1);
            a2 = fmaf(v2, x2, a2);
            a3 = fmaf(v3, x3, a3);
        }
        for (; j < cnt; j++) {
            const int   sj = __shfl_sync(0xffffffffu, ed.x, j);
            const float vj = __int_as_float(__shfl_sync(0xffffffffu, ed.y, j));
            a0 = fmaf(vj, g_xt[(size_t)sj * BB + lane], a0);
        }
    }
    g_yt[(size_t)m * BB + lane] = (a0 + a1) + (a2 + a3);
}

// ---------------------------------------------------------------------------
// 6) transpose yt (M,B) -> out (B,M) + bias
// ---------------------------------------------------------------------------
__global__ void k_transpose_out(float* __restrict__ out,
                                const float* __restrict__ bias) {
    __shared__ float tile[32][33];
    const int m0 = blockIdx.x * 32;
    const int tx = threadIdx.x, ty = threadIdx.y;

    #pragma unroll
    for (int j = 0; j < 4; j++) {
        const int m = m0 + ty + 8 * j;
        tile[ty + 8 * j][tx] = g_yt[(size_t)m * BB + tx];
    }
    __syncthreads();
    const float bv = bias[m0 + tx];
    #pragma unroll
    for (int j = 0; j < 4; j++) {
        const int b = ty + 8 * j;
        out[(size_t)b * MM + m0 + tx] = tile[tx][b] + bv;
    }
}

// ---------------------------------------------------------------------------
extern "C" void kernel_launch(void* const* d_in, const int* in_sizes, int n_in,
                              void* d_out, int out_size) {
    const float* x       = (const float*)d_in[0];   // (B, N, 1)
    const int*   indices = (const int*)  d_in[1];   // (2, NNZ)
    const float* values  = (const float*)d_in[2];   // (NNZ,)
    const float* bias    = (const float*)d_in[3];   // (M, 1)
    float*       out     = (float*)d_out;           // (B, M, 1)
    (void)in_sizes; (void)n_in; (void)out_size;

    // 1) transpose in + zero counts
    k_transpose_in<<<NN / 32, dim3(32, 8)>>>(x);
    // 2) histogram
    k_hist<<<(NNZ / 4 + 255) / 256, 256>>>(indices);
    // 3) scan
    k_scan_a<<<NCHUNK, CHUNK>>>();
    k_scan_b<<<1, 256>>>();
    k_scan_c<<<NCHUNK, CHUNK>>>();
    // 4) reorder into dst-grouped CSR
    k_reorder<<<(NNZ + 255) / 256, 256>>>(indices, values);
    // 5) accumulate (8 warps/block -> 8 dst per block)
    k_accum<<<(MM + 7) / 8, 256>>>();
    // 6) transpose out + bias
    k_transpose_out<<<MM / 32, dim3(32, 8)>>>(out, bias);
}